// round 14
// baseline (speedup 1.0000x reference)
#include <cuda_runtime.h>
#include <cstdint>

#define T_DIM 64
#define U_DIM 142
#define I_DIM 4500
#define B_DIM 16384
#define K_TOP 10
#define WINDOW 24              // probed entries per element (lanes 0..23)

// Per-user argsort of sim row, descending, tie -> lower index first.
// Entry: (float bits << 32) | user index. 161 KB (L2-resident).
__device__ unsigned long long g_sorted[U_DIM * U_DIM];

// ---------------------------------------------------------------------------
// Argsort of each sim row (descending, stable by index). One CTA per user.
// ---------------------------------------------------------------------------
__global__ __launch_bounds__(160) void sort_kernel(const float* __restrict__ sim)
{
    const int u = blockIdx.x;
    const int v = threadIdx.x;
    __shared__ float row[U_DIM];
    if (v < U_DIM) row[v] = sim[u * U_DIM + v];
    __syncthreads();
    if (v >= U_DIM) return;

    const float sv = row[v];
    int rank = 0;
    #pragma unroll 2
    for (int w = 0; w < U_DIM; w++) {
        const float sw = row[w];
        rank += (sw > sv) || (sw == sv && w < v);
    }
    g_sorted[u * U_DIM + rank] =
        ((unsigned long long)__float_as_uint(sv) << 32) | (unsigned)v;
}

// ---------------------------------------------------------------------------
// Predict: ONE WARP per batch element, one window entry per lane (lanes<24).
// Probe qos directly in descending-sim order: the gathered value supplies
// both the rated test (q>0) and the prediction term. Taken set = first K_TOP
// entries with (q>0 && s>0); eligibility is count-independent -> rank filter
// via one ballot + popc.
// ---------------------------------------------------------------------------
__global__ __launch_bounds__(256) void predict_kernel(
    const float* __restrict__ qos,
    const float* __restrict__ user_avg,
    const int*   __restrict__ user_id,
    const int*   __restrict__ item_id,
    const int*   __restrict__ time_id,
    float*       __restrict__ out)
{
    const int warp = (blockIdx.x * blockDim.x + threadIdx.x) >> 5;
    const int lane = threadIdx.x & 31;
    if (warp >= B_DIM) return;
    const int b = warp;

    const int t  = time_id[b];
    const int u  = user_id[b];
    const int it = item_id[b];

    const unsigned long long* srt = g_sorted + u * U_DIM;
    const float* qcol = qos + (size_t)t * U_DIM * I_DIM + it;
    const float* arow = user_avg + t * U_DIM;

    // One probe per lane: sorted entry (L2 hit) -> qos gather (DRAM) + avg.
    float s = 0.f, q = 0.f, a = 0.f;
    bool elig = false;
    if (lane < WINDOW) {
        const unsigned long long ek = __ldg(srt + lane);
        s = __uint_as_float((unsigned)(ek >> 32));
        const int v = (int)(ek & 0xFFFFFFFFull);
        q = __ldg(qcol + (size_t)v * I_DIM);   // scattered DRAM sector
        a = __ldg(arow + v);                   // cache-resident
        elig = (q > 0.f) && (s > 0.f);
    }

    // Rank filter: global eligible-rank via ballot + popc.
    const unsigned full = 0xFFFFFFFFu;
    const unsigned bal  = __ballot_sync(full, elig);
    const int rank       = __popc(bal & ((1u << lane) - 1u));
    const int total_elig = __popc(bal);

    const bool take = elig && (rank < K_TOP);
    float S = take ? s : 0.f;
    float P = take ? s * (q - a) : 0.f;

    // Warp reduce (S, P).
    #pragma unroll
    for (int o = 16; o; o >>= 1) {
        S += __shfl_xor_sync(full, S, o);
        P += __shfl_xor_sync(full, P, o);
    }

    // sim of the last window entry for the tail test.
    const float s_last = __shfl_sync(full, s, WINDOW - 1);

    if (lane == 0) {
        // Rare tail (~2e-4): window had <K eligible and sims still positive.
        if (total_elig < K_TOP && s_last > 0.f) {
            int cnt = total_elig;
            for (int k = WINDOW; k < U_DIM && cnt < K_TOP; k++) {
                const unsigned long long ek = __ldg(srt + k);
                const float ss = __uint_as_float((unsigned)(ek >> 32));
                if (ss <= 0.f) break;
                const int v = (int)(ek & 0xFFFFFFFFull);
                const float qq = __ldg(qcol + (size_t)v * I_DIM);
                if (qq > 0.f) {
                    S += ss;
                    P += ss * (qq - __ldg(arow + v));
                    cnt++;
                }
            }
        }
        const float avg_u = __ldg(arow + u);
        out[b] = avg_u + P / (S + 1e-8f);
    }
}

// ---------------------------------------------------------------------------
extern "C" void kernel_launch(void* const* d_in, const int* in_sizes, int n_in,
                              void* d_out, int out_size) {
    const float* qos      = (const float*)d_in[0];  // [T,U,I]
    const float* user_avg = (const float*)d_in[1];  // [T,U]
    const float* sim      = (const float*)d_in[2];  // [U,U]
    const int*   user_id  = (const int*)d_in[3];    // [B]
    const int*   item_id  = (const int*)d_in[4];    // [B]
    const int*   time_id  = (const int*)d_in[5];    // [B]
    float* out = (float*)d_out;

    sort_kernel<<<U_DIM, 160>>>(sim);

    // One warp per element: 16384 warps = 2048 CTAs x 256 threads.
    predict_kernel<<<(B_DIM * 32) / 256, 256>>>(
        qos, user_avg, user_id, item_id, time_id, out);
}

// round 15
// speedup vs baseline: 1.0201x; 1.0201x over previous
#include <cuda_runtime.h>
#include <cstdint>

#define T_DIM 64
#define U_DIM 142
#define I_DIM 4500
#define B_DIM 16384
#define K_TOP 10
#define PH1 18                 // phase-1 window (lanes 0..17)
#define PH2_END 32             // phase-2 extends window to 32 (lanes 18..31)

// Per-user argsort of sim row, descending, tie -> lower index first.
// Entry: (float bits << 32) | user index. 161 KB (L2-resident).
__device__ unsigned long long g_sorted[U_DIM * U_DIM];

// ---------------------------------------------------------------------------
// Argsort of each sim row (descending, stable by index). One CTA per user.
// ---------------------------------------------------------------------------
__global__ __launch_bounds__(160) void sort_kernel(const float* __restrict__ sim)
{
    const int u = blockIdx.x;
    const int v = threadIdx.x;
    __shared__ float row[U_DIM];
    if (v < U_DIM) row[v] = sim[u * U_DIM + v];
    __syncthreads();
    if (v >= U_DIM) return;

    const float sv = row[v];
    int rank = 0;
    #pragma unroll 2
    for (int w = 0; w < U_DIM; w++) {
        const float sw = row[w];
        rank += (sw > sv) || (sw == sv && w < v);
    }
    g_sorted[u * U_DIM + rank] =
        ((unsigned long long)__float_as_uint(sv) << 32) | (unsigned)v;
}

// ---------------------------------------------------------------------------
// Predict: one warp per batch element; adaptive probe window.
// Phase 1: lanes 0..17 probe the top-18 sorted entries (direct qos probe:
// the gathered value supplies both the rated test and the prediction term).
// Phase 2 (warp-uniform, ~5.5%): lanes 18..31 probe entries 18..31.
// Taken set = first K_TOP eligible (q>0 && s>0) in sorted order -> ballot
// rank filter (lane index == sorted position, so ranking is exact).
// ---------------------------------------------------------------------------
__global__ __launch_bounds__(256) void predict_kernel(
    const float* __restrict__ qos,
    const float* __restrict__ user_avg,
    const int*   __restrict__ user_id,
    const int*   __restrict__ item_id,
    const int*   __restrict__ time_id,
    float*       __restrict__ out)
{
    const int warp = (blockIdx.x * blockDim.x + threadIdx.x) >> 5;
    const int lane = threadIdx.x & 31;
    if (warp >= B_DIM) return;
    const int b = warp;

    const int t  = time_id[b];
    const int u  = user_id[b];
    const int it = item_id[b];

    const unsigned long long* srt = g_sorted + u * U_DIM;
    const float* qcol = qos + (size_t)t * U_DIM * I_DIM + it;
    const float* arow = user_avg + t * U_DIM;

    const unsigned full = 0xFFFFFFFFu;

    float s = 0.f, q = 0.f, a = 0.f;
    bool elig = false;

    // ---- Phase 1: top PH1 entries ----
    if (lane < PH1) {
        const unsigned long long ek = __ldg(srt + lane);
        s = __uint_as_float((unsigned)(ek >> 32));
        const int v = (int)(ek & 0xFFFFFFFFull);
        q = __ldg(qcol + (size_t)v * I_DIM);   // scattered DRAM sector
        a = __ldg(arow + v);                   // cache-resident
        elig = (q > 0.f) && (s > 0.f);
    }

    unsigned bal = __ballot_sync(full, elig);
    int tot = __popc(bal);
    const float s17 = __shfl_sync(full, s, PH1 - 1);

    // ---- Phase 2 (warp-uniform, rare): entries PH1..31 ----
    if (tot < K_TOP && s17 > 0.f) {
        if (lane >= PH1) {
            const unsigned long long ek = __ldg(srt + lane);
            s = __uint_as_float((unsigned)(ek >> 32));
            const int v = (int)(ek & 0xFFFFFFFFull);
            q = __ldg(qcol + (size_t)v * I_DIM);
            a = __ldg(arow + v);
            elig = (q > 0.f) && (s > 0.f);
        }
        bal = __ballot_sync(full, elig);
        tot = __popc(bal);
    }

    // Rank filter: global eligible-rank via popc of lower lanes.
    const int rank = __popc(bal & ((1u << lane) - 1u));
    const bool take = elig && (rank < K_TOP);
    float S = take ? s : 0.f;
    float P = take ? s * (q - a) : 0.f;

    // Warp reduce (S, P).
    #pragma unroll
    for (int o = 16; o; o >>= 1) {
        S += __shfl_xor_sync(full, S, o);
        P += __shfl_xor_sync(full, P, o);
    }

    // Last-entry sim for the tail test (0 unless phase 2 ran -> correct gate).
    const float s31 = __shfl_sync(full, s, 31);

    if (lane == 0) {
        // Ultra-rare tail (~2e-6): 32-entry window still short, sims positive.
        if (tot < K_TOP && s31 > 0.f) {
            int cnt = tot;
            for (int k = PH2_END; k < U_DIM && cnt < K_TOP; k++) {
                const unsigned long long ek = __ldg(srt + k);
                const float ss = __uint_as_float((unsigned)(ek >> 32));
                if (ss <= 0.f) break;
                const int v = (int)(ek & 0xFFFFFFFFull);
                const float qq = __ldg(qcol + (size_t)v * I_DIM);
                if (qq > 0.f) {
                    S += ss;
                    P += ss * (qq - __ldg(arow + v));
                    cnt++;
                }
            }
        }
        const float avg_u = __ldg(arow + u);
        out[b] = avg_u + P / (S + 1e-8f);
    }
}

// ---------------------------------------------------------------------------
extern "C" void kernel_launch(void* const* d_in, const int* in_sizes, int n_in,
                              void* d_out, int out_size) {
    const float* qos      = (const float*)d_in[0];  // [T,U,I]
    const float* user_avg = (const float*)d_in[1];  // [T,U]
    const float* sim      = (const float*)d_in[2];  // [U,U]
    const int*   user_id  = (const int*)d_in[3];    // [B]
    const int*   item_id  = (const int*)d_in[4];    // [B]
    const int*   time_id  = (const int*)d_in[5];    // [B]
    float* out = (float*)d_out;

    sort_kernel<<<U_DIM, 160>>>(sim);

    // One warp per element: 16384 warps = 2048 CTAs x 256 threads.
    predict_kernel<<<(B_DIM * 32) / 256, 256>>>(
        qos, user_avg, user_id, item_id, time_id, out);
}